// round 17
// baseline (speedup 1.0000x reference)
#include <cuda_runtime.h>
#include <math.h>

#define NN 2048
#define FF 128
#define HH 32
#define EE 65536
#define PP 768
#define STRIDE 96            // fixed bucket per node (max in-degree ~52 << 96)
#define FULL 0xffffffffu
#define GRID 148
#define TPB 1024
#define EPB 448              // edges per block (148*448 >= 65536)

typedef unsigned long long ull;

// ---------------- device scratch (no allocations allowed) ----------------
// d_M: 0 = empty, else edge_id+1. Zero at module load. Each launch REWRITES
// exactly the same slot set {(src[e],dst[e])} before any read; non-edge slots
// stay 0 forever -> replay-safe, no cleanup needed.
// d_inlist: only prefixes [d*STRIDE, d*STRIDE+indeg[d]) are read; rewritten
// every launch. d_curd2 zeroed each launch in P4 (after its last read in P3).
// d_indeg rewritten every launch in P3 header before any read.
__device__ int   d_M[NN * NN];
__device__ int   d_curd2[NN];         // in-fill cursor == in-degree when final
__device__ int   d_indeg[NN];         // snapshot (written in P3 header)
__device__ int   d_inlist[NN * STRIDE];   // packed (edge_id<<11)|src, bucketed by dst
__device__ float d_t1[NN * HH];       // x @ W1 (unscaled)
__device__ float d_t2s[NN * HH];      // layer-1 out @ W2, * dinv[row]
__device__ float d_h[NN * HH];
__device__ unsigned          bar_cnt;
__device__ volatile unsigned bar_gen;

__device__ __forceinline__ void gridbar() {
    __syncthreads();
    if (threadIdx.x == 0) {
        __threadfence();
        unsigned g = bar_gen;
        if (atomicAdd(&bar_cnt, 1u) == GRID - 1u) {
            bar_cnt = 0;
            __threadfence();
            bar_gen = g + 1u;
        } else {
            while (bar_gen == g) { }             // tight poll (1 thread/block)
        }
        __threadfence();
    }
    __syncthreads();
}

__device__ __forceinline__ float wsum(float v) {
    #pragma unroll
    for (int o = 16; o; o >>= 1) v += __shfl_xor_sync(FULL, v, o);
    return v;
}

__device__ __forceinline__ ull packf2(float lo, float hi) {
    ull r;
    asm("mov.b64 %0, {%1, %2};" : "=l"(r) : "f"(lo), "f"(hi));
    return r;
}
__device__ __forceinline__ void unpackf2(ull v, float& lo, float& hi) {
    asm("mov.b64 {%0, %1}, %2;" : "=f"(lo), "=f"(hi) : "l"(v));
}
__device__ __forceinline__ ull fma2(ull a, ull b, ull c) {
    ull d;
    asm("fma.rn.f32x2 %0, %1, %2, %3;" : "=l"(d) : "l"(a), "l"(b), "l"(c));
    return d;
}
__device__ __forceinline__ ull add2(ull a, ull b) {
    ull d;
    asm("add.rn.f32x2 %0, %1, %2;" : "=l"(d) : "l"(a), "l"(b));
    return d;
}
__device__ __forceinline__ ull mul2(ull a, ull b) {
    ull d;
    asm("mul.rn.f32x2 %0, %1, %2;" : "=l"(d) : "l"(a), "l"(b));
    return d;
}
// packed butterfly reduction: 2 SHFL + 1 FADD2 per step
__device__ __forceinline__ ull wsum2(ull v) {
    #pragma unroll
    for (int o = 16; o; o >>= 1) v = add2(v, __shfl_xor_sync(FULL, v, o));
    return v;
}

// ================= the whole problem in ONE persistent kernel =================
__global__ void __launch_bounds__(TPB, 1) mega_k(
    const float* __restrict__ x,  const int* __restrict__ ei,  const int* __restrict__ pos,
    const float* __restrict__ W1, const float* __restrict__ b1,
    const float* __restrict__ W2, const float* __restrict__ b2,
    const float* __restrict__ m1w, const float* __restrict__ m1b,
    const float* __restrict__ m1g, const float* __restrict__ m1be,
    const float* __restrict__ m2w, const float* __restrict__ m2b,
    const float* __restrict__ m2g, const float* __restrict__ m2be,
    const float* __restrict__ w31, const float* __restrict__ b31,
    const float* __restrict__ w32, const float* __restrict__ b32,
    float* __restrict__ out)
{
    __shared__ float SM[4096];            // W1 / W2+partials workspace (16 KB)
    __shared__ float dinvs[NN];           // per-node 1/sqrt(deg+1)      (8 KB)
    __shared__ ull   w12s[HH][HH];        // packed (m1w, m2w)            (8 KB)
    __shared__ ull   b12s[HH], g12s[HH], be12s[HH];
    __shared__ float w31s[2 * HH][HH];    // head weights                 (8 KB)
    __shared__ float w32s[HH], b31s[HH];
    const int tid  = threadIdx.x;
    const int warp = tid >> 5, t = tid & 31;
    const int gtid = blockIdx.x * TPB + tid;
    const int* src = ei;
    const int* dst = ei + EE;

    // ---- Pfill: warp-specialized — warps 0-13 gemm1, warps 18-31 edge fill ----
    for (int i = tid; i < FF * HH; i += TPB) SM[i] = W1[i];
    for (int i = tid; i < HH * HH; i += TPB) w12s[i / HH][i % HH] = packf2(m1w[i], m2w[i]);
    for (int i = tid; i < 2 * HH * HH; i += TPB) w31s[i / HH][i % HH] = w31[i];
    if (tid < HH) {
        b12s[tid]  = packf2(m1b[tid],  m2b[tid]);
        g12s[tid]  = packf2(m1g[tid],  m2g[tid]);
        be12s[tid] = packf2(m1be[tid], m2be[tid]);
        w32s[tid] = w32[tid];
        b31s[tid] = b31[tid];
    }
    __syncthreads();
    {
        // edge fill: threads 576..1023 (warps 18-31), contiguous chunk per block
        int le = tid - (TPB - EPB);
        int e  = blockIdx.x * EPB + le;
        if (le >= 0 && e < EE) {
            int s = src[e], d = dst[e];
            d_M[s * NN + d] = e + 1;  // duplicate (s,d) race: value-equivalent winners
            int slot = atomicAdd(&d_curd2[d], 1);
            d_inlist[d * STRIDE + slot] = (e << 11) | s;   // pack (edge, src)
        }
        // gemm1: warps 0-13 (rows balanced across blocks)
        int row = warp * GRID + blockIdx.x;
        if (row < NN) {
            const float* xr = x + row * FF;
            float xa = xr[t], xb = xr[32 + t], xc = xr[64 + t], xd = xr[96 + t];
            float acc = 0.f;
            #pragma unroll
            for (int k = 0; k < 32; k++) {
                acc = fmaf(__shfl_sync(FULL, xa, k), SM[k * HH + t], acc);
                acc = fmaf(__shfl_sync(FULL, xb, k), SM[(k + 32) * HH + t], acc);
                acc = fmaf(__shfl_sync(FULL, xc, k), SM[(k + 64) * HH + t], acc);
                acc = fmaf(__shfl_sync(FULL, xd, k), SM[(k + 96) * HH + t], acc);
            }
            d_t1[row * HH + t] = acc;
        }
    }
    gridbar();

    // ---- P3 header: SMEM dinv table + global indeg snapshot ----
    {
        int c0 = d_curd2[tid];
        int c1 = d_curd2[tid + 1024];
        dinvs[tid]        = rsqrtf((float)(c0 + 1));
        dinvs[tid + 1024] = rsqrtf((float)(c1 + 1));
        d_indeg[tid]        = c0;    // redundant across blocks: same values
        d_indeg[tid + 1024] = c1;
    }
    for (int i = tid; i < HH * HH; i += TPB) SM[i] = W2[i];
    __syncthreads();

    // ---- P3: gather layer1 (SMEM dinv) + GEMM W2 -> t2s ----
    {
        int pairid = warp >> 1, parity = warp & 1;
        int v = blockIdx.x * 16 + pairid;        // 2368 >= NN
        float part = 0.f;
        int cnt = 0;
        if (v < NN) {
            cnt = d_curd2[v];                    // final after barrier
            const int* lst = d_inlist + v * STRIDE;
            int i = parity;
            for (; i + 16 <= cnt; i += 16) {
                int i0 = lst[i] & 2047,      i1 = lst[i + 2] & 2047;
                int i2 = lst[i + 4] & 2047,  i3 = lst[i + 6] & 2047;
                int i4 = lst[i + 8] & 2047,  i5 = lst[i + 10] & 2047;
                int i6 = lst[i + 12] & 2047, i7 = lst[i + 14] & 2047;
                float f0 = d_t1[i0 * HH + t], f1 = d_t1[i1 * HH + t];
                float f2 = d_t1[i2 * HH + t], f3 = d_t1[i3 * HH + t];
                float f4 = d_t1[i4 * HH + t], f5 = d_t1[i5 * HH + t];
                float f6 = d_t1[i6 * HH + t], f7 = d_t1[i7 * HH + t];
                part = fmaf(f0, dinvs[i0], part);
                part = fmaf(f1, dinvs[i1], part);
                part = fmaf(f2, dinvs[i2], part);
                part = fmaf(f3, dinvs[i3], part);
                part = fmaf(f4, dinvs[i4], part);
                part = fmaf(f5, dinvs[i5], part);
                part = fmaf(f6, dinvs[i6], part);
                part = fmaf(f7, dinvs[i7], part);
            }
            for (; i < cnt; i += 2) {
                int s = lst[i] & 2047;
                part = fmaf(d_t1[s * HH + t], dinvs[s], part);
            }
        }
        if (parity && v < NN) SM[1024 + pairid * 32 + t] = part;
        __syncthreads();
        if (!parity && v < NN) {
            float di = dinvs[v];
            float hv = (part + SM[1024 + pairid * 32 + t] + d_t1[v * HH + t] * di) * di + b1[t];
            float y = 0.f;
            #pragma unroll
            for (int k = 0; k < HH; k++)
                y = fmaf(__shfl_sync(FULL, hv, k), SM[k * HH + t], y);
            d_t2s[v * HH + t] = y * di;          // pre-scaled for P4
        }
    }
    gridbar();

    // ---- P4: gather layer2 -> h ; zero fill cursor for next replay ----
    if (gtid < NN) d_curd2[gtid] = 0;            // last read was in P3
    {
        int pairid = warp >> 1, parity = warp & 1;
        int v = blockIdx.x * 16 + pairid;
        float part = 0.f;
        int cnt = 0;
        if (v < NN) {
            cnt = d_indeg[v];
            const int* lst = d_inlist + v * STRIDE;
            int i = parity;
            for (; i + 16 <= cnt; i += 16) {
                int i0 = lst[i] & 2047,      i1 = lst[i + 2] & 2047;
                int i2 = lst[i + 4] & 2047,  i3 = lst[i + 6] & 2047;
                int i4 = lst[i + 8] & 2047,  i5 = lst[i + 10] & 2047;
                int i6 = lst[i + 12] & 2047, i7 = lst[i + 14] & 2047;
                float f0 = d_t2s[i0 * HH + t], f1 = d_t2s[i1 * HH + t];
                float f2 = d_t2s[i2 * HH + t], f3 = d_t2s[i3 * HH + t];
                float f4 = d_t2s[i4 * HH + t], f5 = d_t2s[i5 * HH + t];
                float f6 = d_t2s[i6 * HH + t], f7 = d_t2s[i7 * HH + t];
                part += ((f0 + f1) + (f2 + f3)) + ((f4 + f5) + (f6 + f7));
            }
            for (; i < cnt; i += 2) part += d_t2s[(lst[i] & 2047) * HH + t];
        }
        if (parity && v < NN) SM[pairid * 32 + t] = part;
        __syncthreads();
        if (!parity && v < NN) {
            float di = dinvs[v];
            d_h[v * HH + t] = (part + SM[pairid * 32 + t] + d_t2s[v * HH + t]) * di + b2[t];
        }
    }
    gridbar();

    // ---- P5': warp-per-pair: probe b's IN-list, on-demand edge MLPs, head ----
    {
        int p = blockIdx.x + GRID * warp;        // warps 0-5 active; p < 768
        if (p < PP) {
            int a = pos[p], b = pos[PP + p];
            float ha = d_h[a * HH + t], hb = d_h[b * HH + t];
            float acc = 0.f;
            int cnt = d_indeg[b];
            const int* lst = d_inlist + b * STRIDE;
            const ull c32 = packf2(1.f / 32.f, 1.f / 32.f);
            for (int base = 0; base < cnt; base += 32) {
                int i = base + t;
                int n = 0;
                bool ok = false;
                if (i < cnt) {
                    int v = lst[i];
                    n = v & 2047;
                    int e1 = v >> 11;
                    int m1v = d_M[a * NN + n];   // a->n exists?      (independent)
                    int m2v = d_M[n * NN + b];   // n->b slot owner?  (independent)
                    ok = (m1v != 0) && (m2v == e1 + 1);
                }
                unsigned mask = __ballot_sync(FULL, ok);
                while (mask) {
                    int j = __ffs(mask) - 1; mask &= mask - 1;
                    int nj = __shfl_sync(FULL, n, j);
                    float hn = d_h[nj * HH + t];
                    // packed: lo -> branch1 (edge n->b, m1);  hi -> branch2 (edge a->n, m2)
                    ull xep = packf2(hn * hb, ha * hn);
                    ull y12 = b12s[t];
                    #pragma unroll
                    for (int k = 0; k < HH; k++)
                        y12 = fma2(__shfl_sync(FULL, xep, k), w12s[k][t], y12);
                    ull s12 = wsum2(y12);
                    ull q12 = wsum2(mul2(y12, y12));
                    ull mu12 = mul2(s12, c32);
                    ull nmu  = mu12 ^ 0x8000000080000000ULL;
                    ull v12  = fma2(mu12, nmu, mul2(q12, c32));
                    float v1, v2;
                    unpackf2(v12, v1, v2);
                    ull inv12 = packf2(rsqrtf(v1 + 1e-5f), rsqrtf(v2 + 1e-5f));
                    ull o12 = fma2(mul2(add2(y12, nmu), inv12), g12s[t], be12s[t]);
                    float x1v, x2v;
                    unpackf2(o12, x1v, x2v);                 // x1[n->b], x2[a->n]
                    acc = fmaf(fmaxf(x2v, 0.f), fmaxf(x1v, 0.f), acc);
                }
            }
            float xx = ha * hb;
            float z1 = b31s[t];
            #pragma unroll
            for (int k = 0; k < HH; k++) z1 = fmaf(__shfl_sync(FULL, acc, k), w31s[k][t], z1);
            #pragma unroll
            for (int k = 0; k < HH; k++) z1 = fmaf(__shfl_sync(FULL, xx, k), w31s[HH + k][t], z1);
            z1 = fmaxf(z1, 0.f);
            float r = wsum(z1 * w32s[t]);
            if (t == 0) out[p] = r + b32[0];
        }
    }
}

// ---------------- launch ----------------
extern "C" void kernel_launch(void* const* d_in, const int* in_sizes, int n_in,
                              void* d_out, int out_size) {
    const float* x    = (const float*)d_in[0];
    const int*   ei   = (const int*)  d_in[1];
    const int*   pos  = (const int*)  d_in[2];
    const float* W1   = (const float*)d_in[3];
    const float* b1   = (const float*)d_in[4];
    const float* W2   = (const float*)d_in[5];
    const float* b2   = (const float*)d_in[6];
    const float* m1w  = (const float*)d_in[7];
    const float* m1b  = (const float*)d_in[8];
    const float* m1g  = (const float*)d_in[9];
    const float* m1be = (const float*)d_in[10];
    const float* m2w  = (const float*)d_in[11];
    const float* m2b  = (const float*)d_in[12];
    const float* m2g  = (const float*)d_in[13];
    const float* m2be = (const float*)d_in[14];
    const float* m3w1 = (const float*)d_in[15];
    const float* m3b1 = (const float*)d_in[16];
    const float* m3w2 = (const float*)d_in[17];
    const float* m3b2 = (const float*)d_in[18];
    float* out = (float*)d_out;

    mega_k<<<GRID, TPB>>>(x, ei, pos, W1, b1, W2, b2,
                          m1w, m1b, m1g, m1be, m2w, m2b, m2g, m2be,
                          m3w1, m3b1, m3w2, m3b2, out);
}